// round 13
// baseline (speedup 1.0000x reference)
#include <cuda_runtime.h>

// Shapes (fixed by the problem)
#define BATCH 1024
#define ISZ   1024
#define NH    8
#define HI    8192      // NH * ISZ
#define FEAT  65536     // HI * 8
#define F4    16384     // FEAT / 4

typedef unsigned long long u64;

// ---- f32x2 packed-math helpers (sm_100+; FFMA2 only via PTX) ----
__device__ __forceinline__ u64 pack2(float a, float b) {
    u64 r; asm("mov.b64 %0, {%1,%2};" : "=l"(r) : "f"(a), "f"(b)); return r;
}
__device__ __forceinline__ u64 fma2(u64 a, u64 b, u64 c) {
    u64 r; asm("fma.rn.f32x2 %0, %1, %2, %3;" : "=l"(r) : "l"(a), "l"(b), "l"(c)); return r;
}

// -------- device scratch (no allocations; fully overwritten each run) ----
__device__ float4 g_A[8 * F4];          // monomial coeffs, [n][f/4], f = hi*8 + k
__device__ float  g_B1[8 * ISZ];        // [n][i]  head+scale folded
__device__ float  g_B2[15 * ISZ];       // [p][i]
__device__ float  g_Spart[4 * 2 * ISZ]; // [ix][{sum,sumsq}][b] partials

// ============================================================
// Pass 0 (fused prep+fold): block = 4 i-values x 64 (h,k) pairs.
// Triggers dependent launch (stats) at entry so stats' x-load
// preamble overlaps ALL of prepfold.
// ============================================================
__global__ __launch_bounds__(256) void prepfold_kernel(
    const float* __restrict__ poly,   // [H, I, M]
    const float* __restrict__ kern,   // [H, I, M, K]
    const float* __restrict__ scale)  // [H, I]
{
    // Let the dependent grid (stats) launch immediately.
    cudaTriggerProgrammaticLaunchCompletion();

    __shared__ float part[256 * 25];  // stride 25 -> conflict-free

    int t  = threadIdx.x;
    int il = t >> 6;                  // 0..3 : i within block
    int h  = (t >> 3) & 7;
    int k  = t & 7;
    int i  = blockIdx.x * 4 + il;
    int hi = h * ISZ + i;

    // Chebyshev T_m monomial coefficients C[m][n]
    const float C[8][8] = {
        {  1,  0,  0,  0,   0,    0,  0,  0},
        {  0,  1,  0,  0,   0,    0,  0,  0},
        { -1,  0,  2,  0,   0,    0,  0,  0},
        {  0, -3,  0,  4,   0,    0,  0,  0},
        {  1,  0, -8,  0,   8,    0,  0,  0},
        {  0,  5,  0,-20,   0,   16,  0,  0},
        { -1,  0, 18,  0, -48,    0, 32,  0},
        {  0, -7,  0, 56,   0, -112,  0, 64}};

    float p  = __ldg(&poly[hi * 8 + k]);
    float sc = __ldg(&scale[hi]);
    float W[8];
#pragma unroll
    for (int m = 0; m < 8; m++)
        W[m] = __ldg(&kern[hi * 64 + m * 8 + k]);

    // a[n] = p * sum_m W[m] * C[m][n]
    float a[8];
#pragma unroll
    for (int n = 0; n < 8; n++) {
        float s = 0.0f;
#pragma unroll
        for (int m = 0; m < 8; m++) s = fmaf(W[m], C[m][n], s);
        a[n] = s * p;
    }

    // Write UNSCALED A in [n][f] layout, f = hi*8 + k
    float* Af = reinterpret_cast<float*>(g_A);
#pragma unroll
    for (int n = 0; n < 8; n++) Af[n * FEAT + hi * 8 + k] = a[n];

    // Pre-scale: a'[n] = a[n] * sc^n  -> reductions directly give B1/B2
    {
        float pw = 1.0f;
#pragma unroll
        for (int n = 0; n < 8; n++) { a[n] *= pw; pw *= sc; }
    }

    // Per-thread scaled Gram: q[p] = sum_{n1+n2=p} a'[n1]*a'[n2]
    float q[15];
#pragma unroll
    for (int pp = 0; pp < 15; pp++) q[pp] = 0.0f;
#pragma unroll
    for (int n1 = 0; n1 < 8; n1++)
#pragma unroll
        for (int n2 = 0; n2 < 8; n2++)
            q[n1 + n2] = fmaf(a[n1], a[n2], q[n1 + n2]);

    // Dump 23 values to smem; transpose-reduce over the 64 (h,k) threads per i.
#pragma unroll
    for (int n = 0; n < 8; n++)    part[t * 25 + n]      = a[n];
#pragma unroll
    for (int pp = 0; pp < 15; pp++) part[t * 25 + 8 + pp] = q[pp];
    __syncthreads();

    if (t < 92) {
        int ii = t / 23, j = t % 23;
        float acc0 = 0.0f, acc1 = 0.0f, acc2 = 0.0f, acc3 = 0.0f;
        int base = ii * 64 * 25 + j;
#pragma unroll
        for (int u = 0; u < 64; u += 4) {
            acc0 += part[base + (u    ) * 25];
            acc1 += part[base + (u + 1) * 25];
            acc2 += part[base + (u + 2) * 25];
            acc3 += part[base + (u + 3) * 25];
        }
        float r = (acc0 + acc1) + (acc2 + acc3);
        int gi = blockIdx.x * 4 + ii;
        if (j < 8) g_B1[j * ISZ + gi]       = r;
        else       g_B2[(j - 8) * ISZ + gi] = r;
    }
}

// ============================================================
// Pass 1: per-row sum/sumsq partials. PDL both ways: triggers emit
// at entry; preloads all 16 x values before its own grid sync.
// grid = (4 i-blocks, 64 b-chunks), 256 threads, 16 b-rows/block.
// ============================================================
__global__ __launch_bounds__(256) void stats_kernel(
    const float* __restrict__ x)      // [B, I]
{
    // Let the dependent grid (emit) launch immediately.
    cudaTriggerProgrammaticLaunchCompletion();

    __shared__ float red[16 * 256];

    int i  = blockIdx.x * 256 + threadIdx.x;  // 0..1023
    int ix = blockIdx.x;
    int b0 = blockIdx.y * 16;

    // ---- dependency-free preamble: x loads (overlaps prepfold) ----
    float xv[16];
#pragma unroll
    for (int bb = 0; bb < 16; bb++)
        xv[bb] = __ldg(&x[(b0 + bb) * ISZ + i]);

    // ---- wait for prepfold's B1/B2 ----
    cudaGridDependencySynchronize();

    float b1[8];
#pragma unroll
    for (int n = 0; n < 8; n++) b1[n] = g_B1[n * ISZ + i];
    float b2[15];
#pragma unroll
    for (int pp = 0; pp < 15; pp++) b2[pp] = g_B2[pp * ISZ + i];

    int w    = threadIdx.x >> 5;
    int lane = threadIdx.x & 31;

    for (int tile = 0; tile < 2; tile++) {
        int bt = b0 + tile * 8;
#pragma unroll
        for (int bb = 0; bb < 8; bb++) {
            float xvv = xv[tile * 8 + bb];

            float s1 = b1[7];
#pragma unroll
            for (int n = 6; n >= 0; n--) s1 = fmaf(s1, xvv, b1[n]);
            float s2 = b2[14];
#pragma unroll
            for (int pp = 13; pp >= 0; pp--) s2 = fmaf(s2, xvv, b2[pp]);

            red[(2 * bb)     * 256 + threadIdx.x] = s1;
            red[(2 * bb + 1) * 256 + threadIdx.x] = s2;
        }
        __syncthreads();
#pragma unroll
        for (int s = w; s < 16; s += 8) {
            float v = 0.0f;
#pragma unroll
            for (int j = 0; j < 8; j++) v += red[s * 256 + lane + j * 32];
#pragma unroll
            for (int off = 16; off > 0; off >>= 1)
                v += __shfl_xor_sync(0xFFFFFFFFu, v, off);
            if (lane == 0)
                g_Spart[ix * (2 * ISZ) + (s & 1) * ISZ + bt + (s >> 1)] = v;
        }
        __syncthreads();
    }
}

// ============================================================
// Pass 2: f32x2 Horner (gamma folded), normalize, stream-write.
// PDL: stages x*scale smem tile + gamma/beta packing BEFORE the grid
// dependency sync; only g_A / g_Spart reads wait.
// grid = (64 f-blocks, 64 b-chunks), 256 threads, tile-16 (best).
// ============================================================
__global__ __launch_bounds__(256) void emit_kernel(
    const float* __restrict__ x,
    const float* __restrict__ scale,
    const float* __restrict__ gamma,
    const float* __restrict__ beta,
    float* __restrict__ out)
{
    __shared__ u64 xs2[16 * 128];        // (x*sc, x*sc) duplicated pairs
    __shared__ u64 s_rs2[16];            // (rs, rs)
    __shared__ u64 s_nt2[16];            // (-mu*rs, -mu*rs)

    int f4 = blockIdx.x * 256 + threadIdx.x;   // 0..16383
    int h  = blockIdx.x >> 3;                  // head of this block
    int i0 = (blockIdx.x * 128) & (ISZ - 1);   // tile's base i
    int b0 = blockIdx.y * 16;

    // ---- dependency-free preamble: x*scale staging + gamma/beta ----
    {
        const float4* sc4 = reinterpret_cast<const float4*>(scale + h * ISZ + i0);
#pragma unroll
        for (int t = threadIdx.x; t < 512; t += 256) {
            int bb = t >> 5;
            int c4 = t & 31;
            float4 xv = __ldg(reinterpret_cast<const float4*>(
                                  x + (b0 + bb) * ISZ + i0) + c4);
            float4 s  = __ldg(sc4 + c4);
            int base = bb * 128 + c4 * 4;
            float v0 = xv.x * s.x, v1 = xv.y * s.y, v2 = xv.z * s.z, v3 = xv.w * s.w;
            xs2[base]     = pack2(v0, v0);
            xs2[base + 1] = pack2(v1, v1);
            xs2[base + 2] = pack2(v2, v2);
            xs2[base + 3] = pack2(v3, v3);
        }
    }
    float4 g  = __ldg(reinterpret_cast<const float4*>(gamma) + f4);
    float4 be = __ldg(reinterpret_cast<const float4*>(beta)  + f4);
    u64 g01  = pack2(g.x,  g.y),  g23  = pack2(g.z,  g.w);
    u64 be01 = pack2(be.x, be.y), be23 = pack2(be.z, be.w);

    // ---- wait for prepfold's g_A and stats' g_Spart ----
    cudaGridDependencySynchronize();

    // Inline finalize: sum 4 partials, packed rs / -mu*rs per row
    if (threadIdx.x < 16) {
        const float inv = 1.0f / (float)FEAT;
        int b = b0 + threadIdx.x;
        float s1 = 0.0f, s2 = 0.0f;
#pragma unroll
        for (int ix = 0; ix < 4; ix++) {
            s1 += g_Spart[ix * (2 * ISZ) + b];
            s2 += g_Spart[ix * (2 * ISZ) + ISZ + b];
        }
        float mu  = s1 * inv;
        float var = s2 * inv - mu * mu;
        float rs  = rsqrtf(var + 1e-5f);
        float nt  = -mu * rs;
        s_rs2[threadIdx.x] = pack2(rs, rs);
        s_nt2[threadIdx.x] = pack2(nt, nt);
    }

    // gamma-folded packed coefficients
    u64 c01[8], c23[8];
#pragma unroll
    for (int n = 0; n < 8; n++) {
        float4 cn = g_A[n * F4 + f4];
        c01[n] = pack2(cn.x * g.x, cn.y * g.y);
        c23[n] = pack2(cn.z * g.z, cn.w * g.w);
    }

    __syncthreads();

    int il = threadIdx.x >> 1;                 // local i within tile
    ulonglong2* out2 = reinterpret_cast<ulonglong2*>(out);

#pragma unroll 4
    for (int bb = 0; bb < 16; bb++) {
        u64 xx  = xs2[bb * 128 + il];
        u64 rs2 = s_rs2[bb];
        u64 nt2 = s_nt2[bb];

        u64 y01 = c01[7], y23 = c23[7];
#pragma unroll
        for (int n = 6; n >= 0; n--) {
            y01 = fma2(y01, xx, c01[n]);
            y23 = fma2(y23, xx, c23[n]);
        }

        // o = y*rs + (be - mu*rs*g)
        ulonglong2 v;
        v.x = fma2(y01, rs2, fma2(nt2, g01, be01));
        v.y = fma2(y23, rs2, fma2(nt2, g23, be23));
        __stcs(&out2[(size_t)(b0 + bb) * F4 + f4], v);
    }
}

// ============================================================
extern "C" void kernel_launch(void* const* d_in, const int* in_sizes, int n_in,
                              void* d_out, int out_size)
{
    const float* x     = (const float*)d_in[0];  // [1024, 1024]
    const float* scale = (const float*)d_in[1];  // [8, 1024]
    const float* poly  = (const float*)d_in[2];  // [8, 1024, 8]
    const float* kern  = (const float*)d_in[3];  // [8, 1024, 8, 8]
    const float* gamma = (const float*)d_in[4];  // [65536]
    const float* beta  = (const float*)d_in[5];  // [65536]
    float* out = (float*)d_out;                  // [1024, 65536]

    prepfold_kernel<<<256, 256>>>(poly, kern, scale);

    // PDL: dependent kernels launch as soon as the predecessor triggers,
    // run their dependency-free preamble, then block at
    // cudaGridDependencySynchronize().
    cudaLaunchAttribute attr[1];
    attr[0].id = cudaLaunchAttributeProgrammaticStreamSerialization;
    attr[0].val.programmaticStreamSerializationAllowed = 1;

    {
        cudaLaunchConfig_t cfg = {};
        cfg.gridDim  = dim3(4, 64);
        cfg.blockDim = dim3(256);
        cfg.dynamicSmemBytes = 0;
        cfg.stream = 0;
        cfg.attrs = attr;
        cfg.numAttrs = 1;
        cudaLaunchKernelEx(&cfg, stats_kernel, x);
    }
    {
        cudaLaunchConfig_t cfg = {};
        cfg.gridDim  = dim3(64, 64);
        cfg.blockDim = dim3(256);
        cfg.dynamicSmemBytes = 0;
        cfg.stream = 0;
        cfg.attrs = attr;
        cfg.numAttrs = 1;
        cudaLaunchKernelEx(&cfg, emit_kernel, x, scale, gamma, beta, out);
    }
}

// round 14
// speedup vs baseline: 1.0309x; 1.0309x over previous
#include <cuda_runtime.h>

// Shapes (fixed by the problem)
#define BATCH 1024
#define ISZ   1024
#define NH    8
#define HI    8192      // NH * ISZ
#define FEAT  65536     // HI * 8
#define F4    16384     // FEAT / 4

typedef unsigned long long u64;

// ---- f32x2 packed-math helpers (sm_100+; FFMA2 only via PTX) ----
__device__ __forceinline__ u64 pack2(float a, float b) {
    u64 r; asm("mov.b64 %0, {%1,%2};" : "=l"(r) : "f"(a), "f"(b)); return r;
}
__device__ __forceinline__ u64 fma2(u64 a, u64 b, u64 c) {
    u64 r; asm("fma.rn.f32x2 %0, %1, %2, %3;" : "=l"(r) : "l"(a), "l"(b), "l"(c)); return r;
}

// -------- device scratch (no allocations; fully overwritten each run) ----
__device__ float4 g_A[8 * F4];          // monomial coeffs, [n][f/4], f = hi*8 + k
__device__ float  g_B1[8 * ISZ];        // [n][i]  head+scale folded
__device__ float  g_B2[15 * ISZ];       // [p][i]
__device__ float  g_Spart[4 * 2 * ISZ]; // [ix][{sum,sumsq}][b] partials

// ============================================================
// Pass 0 (fused prep+fold): block = 4 i-values x 64 (h,k) pairs.
// Early PDL trigger: stats (small grid) launches immediately and
// overlaps its x-load preamble with ALL of prepfold. (Emit keeps
// the default completion trigger — early emit flooding regressed.)
// ============================================================
__global__ __launch_bounds__(256) void prepfold_kernel(
    const float* __restrict__ poly,   // [H, I, M]
    const float* __restrict__ kern,   // [H, I, M, K]
    const float* __restrict__ scale)  // [H, I]
{
    // Let the dependent grid (stats) launch immediately.
    cudaTriggerProgrammaticLaunchCompletion();

    __shared__ float part[256 * 25];  // stride 25 -> conflict-free

    int t  = threadIdx.x;
    int il = t >> 6;                  // 0..3 : i within block
    int h  = (t >> 3) & 7;
    int k  = t & 7;
    int i  = blockIdx.x * 4 + il;
    int hi = h * ISZ + i;

    // Chebyshev T_m monomial coefficients C[m][n]
    const float C[8][8] = {
        {  1,  0,  0,  0,   0,    0,  0,  0},
        {  0,  1,  0,  0,   0,    0,  0,  0},
        { -1,  0,  2,  0,   0,    0,  0,  0},
        {  0, -3,  0,  4,   0,    0,  0,  0},
        {  1,  0, -8,  0,   8,    0,  0,  0},
        {  0,  5,  0,-20,   0,   16,  0,  0},
        { -1,  0, 18,  0, -48,    0, 32,  0},
        {  0, -7,  0, 56,   0, -112,  0, 64}};

    float p  = __ldg(&poly[hi * 8 + k]);
    float sc = __ldg(&scale[hi]);
    float W[8];
#pragma unroll
    for (int m = 0; m < 8; m++)
        W[m] = __ldg(&kern[hi * 64 + m * 8 + k]);

    // a[n] = p * sum_m W[m] * C[m][n]
    float a[8];
#pragma unroll
    for (int n = 0; n < 8; n++) {
        float s = 0.0f;
#pragma unroll
        for (int m = 0; m < 8; m++) s = fmaf(W[m], C[m][n], s);
        a[n] = s * p;
    }

    // Write UNSCALED A in [n][f] layout, f = hi*8 + k
    float* Af = reinterpret_cast<float*>(g_A);
#pragma unroll
    for (int n = 0; n < 8; n++) Af[n * FEAT + hi * 8 + k] = a[n];

    // Pre-scale: a'[n] = a[n] * sc^n  -> reductions directly give B1/B2
    {
        float pw = 1.0f;
#pragma unroll
        for (int n = 0; n < 8; n++) { a[n] *= pw; pw *= sc; }
    }

    // Per-thread scaled Gram: q[p] = sum_{n1+n2=p} a'[n1]*a'[n2]
    float q[15];
#pragma unroll
    for (int pp = 0; pp < 15; pp++) q[pp] = 0.0f;
#pragma unroll
    for (int n1 = 0; n1 < 8; n1++)
#pragma unroll
        for (int n2 = 0; n2 < 8; n2++)
            q[n1 + n2] = fmaf(a[n1], a[n2], q[n1 + n2]);

    // Dump 23 values to smem; transpose-reduce over the 64 (h,k) threads per i.
#pragma unroll
    for (int n = 0; n < 8; n++)    part[t * 25 + n]      = a[n];
#pragma unroll
    for (int pp = 0; pp < 15; pp++) part[t * 25 + 8 + pp] = q[pp];
    __syncthreads();

    if (t < 92) {
        int ii = t / 23, j = t % 23;
        float acc0 = 0.0f, acc1 = 0.0f, acc2 = 0.0f, acc3 = 0.0f;
        int base = ii * 64 * 25 + j;
#pragma unroll
        for (int u = 0; u < 64; u += 4) {
            acc0 += part[base + (u    ) * 25];
            acc1 += part[base + (u + 1) * 25];
            acc2 += part[base + (u + 2) * 25];
            acc3 += part[base + (u + 3) * 25];
        }
        float r = (acc0 + acc1) + (acc2 + acc3);
        int gi = blockIdx.x * 4 + ii;
        if (j < 8) g_B1[j * ISZ + gi]       = r;
        else       g_B2[(j - 8) * ISZ + gi] = r;
    }
}

// ============================================================
// Pass 1: per-row sum/sumsq partials. PDL: preloads all 16 x values
// before its grid sync (overlaps prepfold). Default completion
// trigger for emit (no early emit flooding). No atomics.
// grid = (4 i-blocks, 64 b-chunks), 256 threads, 16 b-rows/block.
// ============================================================
__global__ __launch_bounds__(256) void stats_kernel(
    const float* __restrict__ x)      // [B, I]
{
    __shared__ float red[16 * 256];

    int i  = blockIdx.x * 256 + threadIdx.x;  // 0..1023
    int ix = blockIdx.x;
    int b0 = blockIdx.y * 16;

    // ---- dependency-free preamble: x loads (overlaps prepfold) ----
    float xv[16];
#pragma unroll
    for (int bb = 0; bb < 16; bb++)
        xv[bb] = __ldg(&x[(b0 + bb) * ISZ + i]);

    // ---- wait for prepfold's B1/B2 ----
    cudaGridDependencySynchronize();

    float b1[8];
#pragma unroll
    for (int n = 0; n < 8; n++) b1[n] = g_B1[n * ISZ + i];
    float b2[15];
#pragma unroll
    for (int pp = 0; pp < 15; pp++) b2[pp] = g_B2[pp * ISZ + i];

    int w    = threadIdx.x >> 5;
    int lane = threadIdx.x & 31;

    for (int tile = 0; tile < 2; tile++) {
        int bt = b0 + tile * 8;
#pragma unroll
        for (int bb = 0; bb < 8; bb++) {
            float xvv = xv[tile * 8 + bb];

            float s1 = b1[7];
#pragma unroll
            for (int n = 6; n >= 0; n--) s1 = fmaf(s1, xvv, b1[n]);
            float s2 = b2[14];
#pragma unroll
            for (int pp = 13; pp >= 0; pp--) s2 = fmaf(s2, xvv, b2[pp]);

            red[(2 * bb)     * 256 + threadIdx.x] = s1;
            red[(2 * bb + 1) * 256 + threadIdx.x] = s2;
        }
        __syncthreads();
#pragma unroll
        for (int s = w; s < 16; s += 8) {
            float v = 0.0f;
#pragma unroll
            for (int j = 0; j < 8; j++) v += red[s * 256 + lane + j * 32];
#pragma unroll
            for (int off = 16; off > 0; off >>= 1)
                v += __shfl_xor_sync(0xFFFFFFFFu, v, off);
            if (lane == 0)
                g_Spart[ix * (2 * ISZ) + (s & 1) * ISZ + bt + (s >> 1)] = v;
        }
        __syncthreads();
    }
}

// ============================================================
// Pass 2: f32x2 Horner (gamma folded), normalize, stream-write.
// PDL: stages x*scale smem tile + gamma/beta packing BEFORE the grid
// dependency sync; only g_A / g_Spart reads wait.
// grid = (64 f-blocks, 64 b-chunks), 256 threads, tile-16 (best).
// ============================================================
__global__ __launch_bounds__(256) void emit_kernel(
    const float* __restrict__ x,
    const float* __restrict__ scale,
    const float* __restrict__ gamma,
    const float* __restrict__ beta,
    float* __restrict__ out)
{
    __shared__ u64 xs2[16 * 128];        // (x*sc, x*sc) duplicated pairs
    __shared__ u64 s_rs2[16];            // (rs, rs)
    __shared__ u64 s_nt2[16];            // (-mu*rs, -mu*rs)

    int f4 = blockIdx.x * 256 + threadIdx.x;   // 0..16383
    int h  = blockIdx.x >> 3;                  // head of this block
    int i0 = (blockIdx.x * 128) & (ISZ - 1);   // tile's base i
    int b0 = blockIdx.y * 16;

    // ---- dependency-free preamble: x*scale staging + gamma/beta ----
    {
        const float4* sc4 = reinterpret_cast<const float4*>(scale + h * ISZ + i0);
#pragma unroll
        for (int t = threadIdx.x; t < 512; t += 256) {
            int bb = t >> 5;
            int c4 = t & 31;
            float4 xv = __ldg(reinterpret_cast<const float4*>(
                                  x + (b0 + bb) * ISZ + i0) + c4);
            float4 s  = __ldg(sc4 + c4);
            int base = bb * 128 + c4 * 4;
            float v0 = xv.x * s.x, v1 = xv.y * s.y, v2 = xv.z * s.z, v3 = xv.w * s.w;
            xs2[base]     = pack2(v0, v0);
            xs2[base + 1] = pack2(v1, v1);
            xs2[base + 2] = pack2(v2, v2);
            xs2[base + 3] = pack2(v3, v3);
        }
    }
    float4 g  = __ldg(reinterpret_cast<const float4*>(gamma) + f4);
    float4 be = __ldg(reinterpret_cast<const float4*>(beta)  + f4);
    u64 g01  = pack2(g.x,  g.y),  g23  = pack2(g.z,  g.w);
    u64 be01 = pack2(be.x, be.y), be23 = pack2(be.z, be.w);

    // ---- wait for prepfold's g_A and stats' g_Spart ----
    cudaGridDependencySynchronize();

    // Inline finalize: sum 4 partials, packed rs / -mu*rs per row
    if (threadIdx.x < 16) {
        const float inv = 1.0f / (float)FEAT;
        int b = b0 + threadIdx.x;
        float s1 = 0.0f, s2 = 0.0f;
#pragma unroll
        for (int ix = 0; ix < 4; ix++) {
            s1 += g_Spart[ix * (2 * ISZ) + b];
            s2 += g_Spart[ix * (2 * ISZ) + ISZ + b];
        }
        float mu  = s1 * inv;
        float var = s2 * inv - mu * mu;
        float rs  = rsqrtf(var + 1e-5f);
        float nt  = -mu * rs;
        s_rs2[threadIdx.x] = pack2(rs, rs);
        s_nt2[threadIdx.x] = pack2(nt, nt);
    }

    // gamma-folded packed coefficients
    u64 c01[8], c23[8];
#pragma unroll
    for (int n = 0; n < 8; n++) {
        float4 cn = g_A[n * F4 + f4];
        c01[n] = pack2(cn.x * g.x, cn.y * g.y);
        c23[n] = pack2(cn.z * g.z, cn.w * g.w);
    }

    __syncthreads();

    int il = threadIdx.x >> 1;                 // local i within tile
    ulonglong2* out2 = reinterpret_cast<ulonglong2*>(out);

#pragma unroll 4
    for (int bb = 0; bb < 16; bb++) {
        u64 xx  = xs2[bb * 128 + il];
        u64 rs2 = s_rs2[bb];
        u64 nt2 = s_nt2[bb];

        u64 y01 = c01[7], y23 = c23[7];
#pragma unroll
        for (int n = 6; n >= 0; n--) {
            y01 = fma2(y01, xx, c01[n]);
            y23 = fma2(y23, xx, c23[n]);
        }

        // o = y*rs + (be - mu*rs*g)
        ulonglong2 v;
        v.x = fma2(y01, rs2, fma2(nt2, g01, be01));
        v.y = fma2(y23, rs2, fma2(nt2, g23, be23));
        __stcs(&out2[(size_t)(b0 + bb) * F4 + f4], v);
    }
}

// ============================================================
extern "C" void kernel_launch(void* const* d_in, const int* in_sizes, int n_in,
                              void* d_out, int out_size)
{
    const float* x     = (const float*)d_in[0];  // [1024, 1024]
    const float* scale = (const float*)d_in[1];  // [8, 1024]
    const float* poly  = (const float*)d_in[2];  // [8, 1024, 8]
    const float* kern  = (const float*)d_in[3];  // [8, 1024, 8, 8]
    const float* gamma = (const float*)d_in[4];  // [65536]
    const float* beta  = (const float*)d_in[5];  // [65536]
    float* out = (float*)d_out;                  // [1024, 65536]

    prepfold_kernel<<<256, 256>>>(poly, kern, scale);

    // PDL: dependent kernels run dependency-free preambles, then block at
    // cudaGridDependencySynchronize(). stats launches early (prepfold
    // triggers at entry); emit launches at stats completion (default).
    cudaLaunchAttribute attr[1];
    attr[0].id = cudaLaunchAttributeProgrammaticStreamSerialization;
    attr[0].val.programmaticStreamSerializationAllowed = 1;

    {
        cudaLaunchConfig_t cfg = {};
        cfg.gridDim  = dim3(4, 64);
        cfg.blockDim = dim3(256);
        cfg.dynamicSmemBytes = 0;
        cfg.stream = 0;
        cfg.attrs = attr;
        cfg.numAttrs = 1;
        cudaLaunchKernelEx(&cfg, stats_kernel, x);
    }
    {
        cudaLaunchConfig_t cfg = {};
        cfg.gridDim  = dim3(64, 64);
        cfg.blockDim = dim3(256);
        cfg.dynamicSmemBytes = 0;
        cfg.stream = 0;
        cfg.attrs = attr;
        cfg.numAttrs = 1;
        cudaLaunchKernelEx(&cfg, emit_kernel, x, scale, gamma, beta, out);
    }
}

// round 15
// speedup vs baseline: 1.0400x; 1.0088x over previous
#include <cuda_runtime.h>

// Shapes (fixed by the problem)
#define BATCH 1024
#define ISZ   1024
#define NH    8
#define HI    8192      // NH * ISZ
#define FEAT  65536     // HI * 8
#define F4    16384     // FEAT / 4

typedef unsigned long long u64;

// ---- f32x2 packed-math helpers (sm_100+; FFMA2 only via PTX) ----
__device__ __forceinline__ u64 pack2(float a, float b) {
    u64 r; asm("mov.b64 %0, {%1,%2};" : "=l"(r) : "f"(a), "f"(b)); return r;
}
__device__ __forceinline__ u64 fma2(u64 a, u64 b, u64 c) {
    u64 r; asm("fma.rn.f32x2 %0, %1, %2, %3;" : "=l"(r) : "l"(a), "l"(b), "l"(c)); return r;
}

// -------- device scratch (no allocations; fully overwritten each run) ----
__device__ float4 g_A[8 * F4];          // monomial coeffs, [n][f/4], f = hi*8 + k
__device__ float  g_B1[8 * ISZ];        // [n][i]  head+scale folded
__device__ float  g_B2[15 * ISZ];       // [p][i]
__device__ float  g_Spart[4 * 2 * ISZ]; // [ix][{sum,sumsq}][b] partials

// ============================================================
// Pass 0 (fused prep+fold): block = 4 i-values x 64 (h,k) pairs.
// Early PDL trigger: stats (small grid) launches immediately and
// overlaps its x-load preamble with ALL of prepfold.
// ============================================================
__global__ __launch_bounds__(256) void prepfold_kernel(
    const float* __restrict__ poly,   // [H, I, M]
    const float* __restrict__ kern,   // [H, I, M, K]
    const float* __restrict__ scale)  // [H, I]
{
    // Let the dependent grid (stats) launch immediately.
    cudaTriggerProgrammaticLaunchCompletion();

    __shared__ float part[256 * 25];  // stride 25 -> conflict-free

    int t  = threadIdx.x;
    int il = t >> 6;                  // 0..3 : i within block
    int h  = (t >> 3) & 7;
    int k  = t & 7;
    int i  = blockIdx.x * 4 + il;
    int hi = h * ISZ + i;

    // Chebyshev T_m monomial coefficients C[m][n]
    const float C[8][8] = {
        {  1,  0,  0,  0,   0,    0,  0,  0},
        {  0,  1,  0,  0,   0,    0,  0,  0},
        { -1,  0,  2,  0,   0,    0,  0,  0},
        {  0, -3,  0,  4,   0,    0,  0,  0},
        {  1,  0, -8,  0,   8,    0,  0,  0},
        {  0,  5,  0,-20,   0,   16,  0,  0},
        { -1,  0, 18,  0, -48,    0, 32,  0},
        {  0, -7,  0, 56,   0, -112,  0, 64}};

    float p  = __ldg(&poly[hi * 8 + k]);
    float sc = __ldg(&scale[hi]);
    float W[8];
#pragma unroll
    for (int m = 0; m < 8; m++)
        W[m] = __ldg(&kern[hi * 64 + m * 8 + k]);

    // a[n] = p * sum_m W[m] * C[m][n]
    float a[8];
#pragma unroll
    for (int n = 0; n < 8; n++) {
        float s = 0.0f;
#pragma unroll
        for (int m = 0; m < 8; m++) s = fmaf(W[m], C[m][n], s);
        a[n] = s * p;
    }

    // Write UNSCALED A in [n][f] layout, f = hi*8 + k
    float* Af = reinterpret_cast<float*>(g_A);
#pragma unroll
    for (int n = 0; n < 8; n++) Af[n * FEAT + hi * 8 + k] = a[n];

    // Pre-scale: a'[n] = a[n] * sc^n  -> reductions directly give B1/B2
    {
        float pw = 1.0f;
#pragma unroll
        for (int n = 0; n < 8; n++) { a[n] *= pw; pw *= sc; }
    }

    // Per-thread scaled Gram: q[p] = sum_{n1+n2=p} a'[n1]*a'[n2]
    float q[15];
#pragma unroll
    for (int pp = 0; pp < 15; pp++) q[pp] = 0.0f;
#pragma unroll
    for (int n1 = 0; n1 < 8; n1++)
#pragma unroll
        for (int n2 = 0; n2 < 8; n2++)
            q[n1 + n2] = fmaf(a[n1], a[n2], q[n1 + n2]);

    // Dump 23 values to smem; transpose-reduce over the 64 (h,k) threads per i.
#pragma unroll
    for (int n = 0; n < 8; n++)    part[t * 25 + n]      = a[n];
#pragma unroll
    for (int pp = 0; pp < 15; pp++) part[t * 25 + 8 + pp] = q[pp];
    __syncthreads();

    if (t < 92) {
        int ii = t / 23, j = t % 23;
        float acc0 = 0.0f, acc1 = 0.0f, acc2 = 0.0f, acc3 = 0.0f;
        int base = ii * 64 * 25 + j;
#pragma unroll
        for (int u = 0; u < 64; u += 4) {
            acc0 += part[base + (u    ) * 25];
            acc1 += part[base + (u + 1) * 25];
            acc2 += part[base + (u + 2) * 25];
            acc3 += part[base + (u + 3) * 25];
        }
        float r = (acc0 + acc1) + (acc2 + acc3);
        int gi = blockIdx.x * 4 + ii;
        if (j < 8) g_B1[j * ISZ + gi]       = r;
        else       g_B2[(j - 8) * ISZ + gi] = r;
    }
}

// ============================================================
// Pass 1: per-row sum/sumsq partials. 8 b-rows/block (grid (4,128)):
// halves the post-sync exposed critical path vs 16-row blocks and
// doubles block-level parallelism of the exposed segment.
// PDL: preloads the 8 x values before the grid sync. No atomics.
// ============================================================
__global__ __launch_bounds__(256) void stats_kernel(
    const float* __restrict__ x)      // [B, I]
{
    __shared__ float red[16 * 256];

    int i  = blockIdx.x * 256 + threadIdx.x;  // 0..1023
    int ix = blockIdx.x;
    int b0 = blockIdx.y * 8;

    // ---- dependency-free preamble: x loads (overlaps prepfold) ----
    float xv[8];
#pragma unroll
    for (int bb = 0; bb < 8; bb++)
        xv[bb] = __ldg(&x[(b0 + bb) * ISZ + i]);

    // ---- wait for prepfold's B1/B2 ----
    cudaGridDependencySynchronize();

    float b1[8];
#pragma unroll
    for (int n = 0; n < 8; n++) b1[n] = g_B1[n * ISZ + i];
    float b2[15];
#pragma unroll
    for (int pp = 0; pp < 15; pp++) b2[pp] = g_B2[pp * ISZ + i];

    int w    = threadIdx.x >> 5;
    int lane = threadIdx.x & 31;

#pragma unroll
    for (int bb = 0; bb < 8; bb++) {
        float xvv = xv[bb];

        float s1 = b1[7];
#pragma unroll
        for (int n = 6; n >= 0; n--) s1 = fmaf(s1, xvv, b1[n]);
        float s2 = b2[14];
#pragma unroll
        for (int pp = 13; pp >= 0; pp--) s2 = fmaf(s2, xvv, b2[pp]);

        red[(2 * bb)     * 256 + threadIdx.x] = s1;
        red[(2 * bb + 1) * 256 + threadIdx.x] = s2;
    }
    __syncthreads();
#pragma unroll
    for (int s = w; s < 16; s += 8) {
        float v = 0.0f;
#pragma unroll
        for (int j = 0; j < 8; j++) v += red[s * 256 + lane + j * 32];
#pragma unroll
        for (int off = 16; off > 0; off >>= 1)
            v += __shfl_xor_sync(0xFFFFFFFFu, v, off);
        if (lane == 0)
            g_Spart[ix * (2 * ISZ) + (s & 1) * ISZ + b0 + (s >> 1)] = v;
    }
}

// ============================================================
// Pass 2: f32x2 Horner (gamma folded), normalize, stream-write.
// PDL: stages x*scale smem tile + gamma/beta packing BEFORE the grid
// dependency sync; only g_A / g_Spart reads wait. Tile-16 (best).
// grid = (64 f-blocks, 64 b-chunks), 256 threads.
// ============================================================
__global__ __launch_bounds__(256) void emit_kernel(
    const float* __restrict__ x,
    const float* __restrict__ scale,
    const float* __restrict__ gamma,
    const float* __restrict__ beta,
    float* __restrict__ out)
{
    __shared__ u64 xs2[16 * 128];        // (x*sc, x*sc) duplicated pairs
    __shared__ u64 s_rs2[16];            // (rs, rs)
    __shared__ u64 s_nt2[16];            // (-mu*rs, -mu*rs)

    int f4 = blockIdx.x * 256 + threadIdx.x;   // 0..16383
    int h  = blockIdx.x >> 3;                  // head of this block
    int i0 = (blockIdx.x * 128) & (ISZ - 1);   // tile's base i
    int b0 = blockIdx.y * 16;

    // ---- dependency-free preamble: x*scale staging + gamma/beta ----
    {
        const float4* sc4 = reinterpret_cast<const float4*>(scale + h * ISZ + i0);
#pragma unroll
        for (int t = threadIdx.x; t < 512; t += 256) {
            int bb = t >> 5;
            int c4 = t & 31;
            float4 xv = __ldg(reinterpret_cast<const float4*>(
                                  x + (b0 + bb) * ISZ + i0) + c4);
            float4 s  = __ldg(sc4 + c4);
            int base = bb * 128 + c4 * 4;
            float v0 = xv.x * s.x, v1 = xv.y * s.y, v2 = xv.z * s.z, v3 = xv.w * s.w;
            xs2[base]     = pack2(v0, v0);
            xs2[base + 1] = pack2(v1, v1);
            xs2[base + 2] = pack2(v2, v2);
            xs2[base + 3] = pack2(v3, v3);
        }
    }
    float4 g  = __ldg(reinterpret_cast<const float4*>(gamma) + f4);
    float4 be = __ldg(reinterpret_cast<const float4*>(beta)  + f4);
    u64 g01  = pack2(g.x,  g.y),  g23  = pack2(g.z,  g.w);
    u64 be01 = pack2(be.x, be.y), be23 = pack2(be.z, be.w);

    // ---- wait for prepfold's g_A and stats' g_Spart ----
    cudaGridDependencySynchronize();

    // Inline finalize: sum 4 partials, packed rs / -mu*rs per row
    if (threadIdx.x < 16) {
        const float inv = 1.0f / (float)FEAT;
        int b = b0 + threadIdx.x;
        float s1 = 0.0f, s2 = 0.0f;
#pragma unroll
        for (int ix = 0; ix < 4; ix++) {
            s1 += g_Spart[ix * (2 * ISZ) + b];
            s2 += g_Spart[ix * (2 * ISZ) + ISZ + b];
        }
        float mu  = s1 * inv;
        float var = s2 * inv - mu * mu;
        float rs  = rsqrtf(var + 1e-5f);
        float nt  = -mu * rs;
        s_rs2[threadIdx.x] = pack2(rs, rs);
        s_nt2[threadIdx.x] = pack2(nt, nt);
    }

    // gamma-folded packed coefficients
    u64 c01[8], c23[8];
#pragma unroll
    for (int n = 0; n < 8; n++) {
        float4 cn = g_A[n * F4 + f4];
        c01[n] = pack2(cn.x * g.x, cn.y * g.y);
        c23[n] = pack2(cn.z * g.z, cn.w * g.w);
    }

    __syncthreads();

    int il = threadIdx.x >> 1;                 // local i within tile
    ulonglong2* out2 = reinterpret_cast<ulonglong2*>(out);

#pragma unroll 4
    for (int bb = 0; bb < 16; bb++) {
        u64 xx  = xs2[bb * 128 + il];
        u64 rs2 = s_rs2[bb];
        u64 nt2 = s_nt2[bb];

        u64 y01 = c01[7], y23 = c23[7];
#pragma unroll
        for (int n = 6; n >= 0; n--) {
            y01 = fma2(y01, xx, c01[n]);
            y23 = fma2(y23, xx, c23[n]);
        }

        // o = y*rs + (be - mu*rs*g)
        ulonglong2 v;
        v.x = fma2(y01, rs2, fma2(nt2, g01, be01));
        v.y = fma2(y23, rs2, fma2(nt2, g23, be23));
        __stcs(&out2[(size_t)(b0 + bb) * F4 + f4], v);
    }
}

// ============================================================
extern "C" void kernel_launch(void* const* d_in, const int* in_sizes, int n_in,
                              void* d_out, int out_size)
{
    const float* x     = (const float*)d_in[0];  // [1024, 1024]
    const float* scale = (const float*)d_in[1];  // [8, 1024]
    const float* poly  = (const float*)d_in[2];  // [8, 1024, 8]
    const float* kern  = (const float*)d_in[3];  // [8, 1024, 8, 8]
    const float* gamma = (const float*)d_in[4];  // [65536]
    const float* beta  = (const float*)d_in[5];  // [65536]
    float* out = (float*)d_out;                  // [1024, 65536]

    prepfold_kernel<<<256, 256>>>(poly, kern, scale);

    // PDL: dependent kernels run dependency-free preambles, then block at
    // cudaGridDependencySynchronize(). stats launches early (prepfold
    // triggers at entry); emit launches at stats completion (default).
    cudaLaunchAttribute attr[1];
    attr[0].id = cudaLaunchAttributeProgrammaticStreamSerialization;
    attr[0].val.programmaticStreamSerializationAllowed = 1;

    {
        cudaLaunchConfig_t cfg = {};
        cfg.gridDim  = dim3(4, 128);
        cfg.blockDim = dim3(256);
        cfg.dynamicSmemBytes = 0;
        cfg.stream = 0;
        cfg.attrs = attr;
        cfg.numAttrs = 1;
        cudaLaunchKernelEx(&cfg, stats_kernel, x);
    }
    {
        cudaLaunchConfig_t cfg = {};
        cfg.gridDim  = dim3(64, 64);
        cfg.blockDim = dim3(256);
        cfg.dynamicSmemBytes = 0;
        cfg.stream = 0;
        cfg.attrs = attr;
        cfg.numAttrs = 1;
        cudaLaunchKernelEx(&cfg, emit_kernel, x, scale, gamma, beta, out);
    }
}